// round 3
// baseline (speedup 1.0000x reference)
#include <cuda_runtime.h>
#include <cuda_fp16.h>
#include <cstdint>

#define VOCAB 32000
#define EMBD  1024
#define HID   1024
#define BATCH 16
#define SEQ   512
#define NTOK  (BATCH*SEQ)

__device__ __half g_x  [(size_t)NTOK*EMBD];
__device__ __half g_y0 [(size_t)NTOK*HID];
__device__ __half g_y1 [(size_t)NTOK*HID];
__device__ float  g_pre[(size_t)NTOK*HID];
__device__ __half g_Wih0h[(size_t)HID*EMBD];
__device__ __half g_Whh0h[(size_t)HID*HID];
__device__ __half g_Wih1h[(size_t)HID*HID];
__device__ __half g_Whh1h[(size_t)HID*HID];
__device__ __half g_fcwh [(size_t)VOCAB*HID];
__device__ float  g_b0[HID];
__device__ float  g_b1[HID];
__device__ __half g_h[2][BATCH*HID];
__device__ unsigned g_cnt0[SEQ];
__device__ unsigned g_cnt1[SEQ];

__device__ __forceinline__ uint32_t smem_u32(const void* p){
    return (uint32_t)__cvta_generic_to_shared(p);
}
__device__ __forceinline__ void ldsm_x4(uint32_t &r0,uint32_t &r1,uint32_t &r2,uint32_t &r3,uint32_t a){
    asm volatile("ldmatrix.sync.aligned.m8n8.x4.shared.b16 {%0,%1,%2,%3}, [%4];"
        : "=r"(r0),"=r"(r1),"=r"(r2),"=r"(r3) : "r"(a));
}
__device__ __forceinline__ void ldsm_x2(uint32_t &r0,uint32_t &r1,uint32_t a){
    asm volatile("ldmatrix.sync.aligned.m8n8.x2.shared.b16 {%0,%1}, [%2];"
        : "=r"(r0),"=r"(r1) : "r"(a));
}
__device__ __forceinline__ void mma16816(float c[4], const uint32_t a[4], const uint32_t b[2]){
    asm volatile(
      "mma.sync.aligned.m16n8k16.row.col.f32.f16.f16.f32 "
      "{%0,%1,%2,%3}, {%4,%5,%6,%7}, {%8,%9}, {%0,%1,%2,%3};"
      : "+f"(c[0]), "+f"(c[1]), "+f"(c[2]), "+f"(c[3])
      : "r"(a[0]), "r"(a[1]), "r"(a[2]), "r"(a[3]), "r"(b[0]), "r"(b[1]));
}
__device__ __forceinline__ void cp_async16(void* s, const void* g){
    asm volatile("cp.async.cg.shared.global [%0], [%1], 16;" :: "r"(smem_u32(s)), "l"(g));
}
#define CP_COMMIT() asm volatile("cp.async.commit_group;")
#define CP_WAIT0()  asm volatile("cp.async.wait_group 0;")

__device__ __forceinline__ unsigned ld_acq(const unsigned* p){
    unsigned v;
    asm volatile("ld.acquire.gpu.global.u32 %0, [%1];" : "=r"(v) : "l"(p) : "memory");
    return v;
}
__device__ __forceinline__ void red_rel(unsigned* p){
    asm volatile("red.release.gpu.global.add.u32 [%0], 1;" :: "l"(p) : "memory");
}

// ---- prep: weights -> fp16, bias sums, counters reset -----------------------
__global__ void prep_kernel(const float* __restrict__ Wih0, const float* __restrict__ Whh0,
                            const float* __restrict__ bih0, const float* __restrict__ bhh0,
                            const float* __restrict__ Wih1, const float* __restrict__ Whh1,
                            const float* __restrict__ bih1, const float* __restrict__ bhh1,
                            const float* __restrict__ fcw)
{
    size_t gtid = (size_t)blockIdx.x*blockDim.x + threadIdx.x;
    size_t gs   = (size_t)gridDim.x*blockDim.x;
    const size_t NW = (size_t)HID*HID;
    for (size_t i = gtid; i < NW; i += gs){
        g_Wih0h[i] = __float2half(Wih0[i]);
        g_Whh0h[i] = __float2half(Whh0[i]);
        g_Wih1h[i] = __float2half(Wih1[i]);
        g_Whh1h[i] = __float2half(Whh1[i]);
    }
    const size_t NF4 = (size_t)VOCAB*HID/4;
    for (size_t i = gtid; i < NF4; i += gs){
        float4 v = ((const float4*)fcw)[i];
        __half2* dst = (__half2*)&g_fcwh[i*4];
        dst[0] = __floats2half2_rn(v.x, v.y);
        dst[1] = __floats2half2_rn(v.z, v.w);
    }
    for (size_t i = gtid; i < HID; i += gs){
        g_b0[i] = bih0[i] + bhh0[i];
        g_b1[i] = bih1[i] + bhh1[i];
    }
    for (size_t i = gtid; i < SEQ; i += gs){ g_cnt0[i] = 0; g_cnt1[i] = 0; }
}

// ---- embedding gather -------------------------------------------------------
__global__ void embed_kernel(const int* __restrict__ ids, const float* __restrict__ emb)
{
    int m = blockIdx.x;
    int row = ids[m];
    const float4* src = (const float4*)(emb + (size_t)row*EMBD);
    __half2* dst = (__half2*)(g_x + (size_t)m*EMBD);
    int t = threadIdx.x;
    float4 v = src[t];
    dst[t*2 + 0] = __floats2half2_rn(v.x, v.y);
    dst[t*2 + 1] = __floats2half2_rn(v.z, v.w);
}

// ---- C[M,N] = A[M,K]*B[N,K]^T + bias; 128x128x32 tile, 8 warps --------------
template<bool TIME_MAJOR>
__global__ void __launch_bounds__(256) gemm_tn(
    const __half* __restrict__ A, const __half* __restrict__ B,
    const float* __restrict__ bias, float* __restrict__ C, int N, int K)
{
    constexpr int BM=128, BN=128, BK=32, STR=BK+8;
    __shared__ __align__(16) __half As[2][BM*STR];
    __shared__ __align__(16) __half Bs[2][BN*STR];

    const int tid  = threadIdx.x;
    const int lane = tid & 31, wid = tid >> 5;
    const int m0 = blockIdx.x*BM, n0 = blockIdx.y*BN;
    const int wm = (wid & 3)*32, wn = (wid >> 2)*64;

    float acc[2][8][4];
    #pragma unroll
    for (int a=0;a<2;a++) for (int b=0;b<8;b++) for (int c=0;c<4;c++) acc[a][b][c]=0.f;

    auto load_tiles = [&](int buf, int k0){
        #pragma unroll
        for (int i=0;i<2;i++){
            int c = tid*2 + i;
            int r = c >> 2, kc = (c & 3)*8;
            cp_async16(&As[buf][r*STR + kc], &A[(size_t)(m0+r)*K + k0 + kc]);
            cp_async16(&Bs[buf][r*STR + kc], &B[(size_t)(n0+r)*K + k0 + kc]);
        }
    };

    const int KT = K/BK;
    load_tiles(0, 0); CP_COMMIT();
    int buf = 0;
    for (int kt = 0; kt < KT; kt++){
        CP_WAIT0(); __syncthreads();
        if (kt + 1 < KT){ load_tiles(buf^1, (kt+1)*BK); CP_COMMIT(); }
        #pragma unroll
        for (int kk = 0; kk < 2; kk++){
            uint32_t a[2][4];
            #pragma unroll
            for (int mi=0; mi<2; mi++){
                int r  = wm + mi*16 + (lane & 15);
                int kc = kk*16 + (lane >> 4)*8;
                ldsm_x4(a[mi][0],a[mi][1],a[mi][2],a[mi][3], smem_u32(&As[buf][r*STR + kc]));
            }
            uint32_t bb[8][2];
            #pragma unroll
            for (int np=0; np<4; np++){
                int gq = lane >> 3;
                int nr = wn + np*16 + (lane & 7) + ((gq >> 1) << 3);
                int kc = kk*16 + ((gq & 1) << 3);
                uint32_t r0,r1,r2,r3;
                ldsm_x4(r0,r1,r2,r3, smem_u32(&Bs[buf][nr*STR + kc]));
                bb[np*2][0]=r0; bb[np*2][1]=r1; bb[np*2+1][0]=r2; bb[np*2+1][1]=r3;
            }
            #pragma unroll
            for (int mi=0; mi<2; mi++)
                #pragma unroll
                for (int ni=0; ni<8; ni++)
                    mma16816(acc[mi][ni], a[mi], bb[ni]);
        }
        buf ^= 1;
    }

    #pragma unroll
    for (int mi=0; mi<2; mi++){
        #pragma unroll
        for (int ni=0; ni<8; ni++){
            int col = n0 + wn + ni*8 + (lane & 3)*2;
            float bv0 = bias[col], bv1 = bias[col+1];
            #pragma unroll
            for (int h=0; h<2; h++){
                int row = m0 + wm + mi*16 + (lane >> 2) + h*8;
                size_t orow = TIME_MAJOR ? (size_t)((row & (SEQ-1))*BATCH + (row >> 9))
                                         : (size_t)row;
                float2 v = make_float2(acc[mi][ni][h*2+0] + bv0,
                                       acc[mi][ni][h*2+1] + bv1);
                *(float2*)&C[orow*(size_t)N + col] = v;
            }
        }
    }
}

// ---- persistent RNN layer: 32 CTAs x 256 thr, Whh slice resident ------------
// pre time-major [t][b][h] f32; y out [b*SEQ+t][h] fp16; hid f32 [B][H]
__global__ void __launch_bounds__(256,1) rnn_layer(
    const float* __restrict__ pre, const __half* __restrict__ Whh,
    __half* __restrict__ y, float* __restrict__ hid, unsigned* __restrict__ cnt)
{
    constexpr int SK = HID + 8;                 // padded half stride
    extern __shared__ __align__(16) __half sm[];
    __half* Ws = sm;                            // [32][SK]
    __half* Hs = sm + 32*SK;                    // [16][SK]
    __shared__ float red[4][32][4];

    const int tid  = threadIdx.x;
    const int lane = tid & 31, wid = tid >> 5;
    const int cb   = blockIdx.x * 32;           // this CTA's column base
    const int nw   = (wid & 3) * 8;             // warp's 8-col tile
    const int kh   = wid >> 2;                  // k-half: 0 or 1

    // stage Whh slice [32][1024] once
    for (int c = tid; c < 32*128; c += 256){
        int n = c >> 7, q = c & 127;
        *(uint4*)&Ws[n*SK + q*8] = *(const uint4*)&Whh[(size_t)(cb+n)*HID + q*8];
    }
    __syncthreads();

    for (int t = 0; t < SEQ; t++){
        float acc[4] = {0.f,0.f,0.f,0.f};
        if (t > 0){
            if (tid == 0){ while (ld_acq(&cnt[t-1]) < 32) {} }
            __syncthreads();
            const __half* hsrc = g_h[(t-1)&1];
            // stage h [16][1024] via L2 (__ldcg: L1 not coherent across SMs)
            for (int c = tid; c < 16*128; c += 256){
                int b = c >> 7, q = c & 127;
                float4 v = __ldcg((const float4*)&hsrc[(size_t)b*HID + q*8]);
                *(float4*)&Hs[b*SK + q*8] = v;
            }
            __syncthreads();
            #pragma unroll 4
            for (int kt = 0; kt < 32; kt++){
                int kg = kh*32 + kt;
                uint32_t a[4];
                ldsm_x4(a[0],a[1],a[2],a[3],
                        smem_u32(&Hs[(lane&15)*SK + kg*16 + (lane>>4)*8]));
                uint32_t b0,b1;
                ldsm_x2(b0,b1,
                        smem_u32(&Ws[(nw + (lane&7))*SK + kg*16 + (((lane>>3)&1)<<3)]));
                uint32_t bb[2] = {b0,b1};
                mma16816(acc, a, bb);
            }
            // K-split reduce: warps 4-7 hand partials to warps 0-3
            if (kh == 1){
                #pragma unroll
                for (int i=0;i<4;i++) red[wid-4][lane][i] = acc[i];
            }
            __syncthreads();
            if (kh == 0){
                #pragma unroll
                for (int i=0;i<4;i++) acc[i] += red[wid][lane][i];
            }
        }
        if (kh == 0){
            int b1 = lane >> 2, b2 = b1 + 8;
            int jj = nw + (lane & 3)*2;
            int col = cb + jj;
            float2 p1 = *(const float2*)&pre[(size_t)t*BATCH*HID + b1*HID + col];
            float2 p2 = *(const float2*)&pre[(size_t)t*BATCH*HID + b2*HID + col];
            float v0 = tanhf(acc[0] + p1.x), v1 = tanhf(acc[1] + p1.y);
            float v2 = tanhf(acc[2] + p2.x), v3 = tanhf(acc[3] + p2.y);
            __half2 h1 = __floats2half2_rn(v0, v1);
            __half2 h2 = __floats2half2_rn(v2, v3);
            __half* hdst = g_h[t & 1];
            *(__half2*)&hdst[b1*HID + col] = h1;
            *(__half2*)&hdst[b2*HID + col] = h2;
            *(__half2*)&y[((size_t)b1*SEQ + t)*HID + col] = h1;
            *(__half2*)&y[((size_t)b2*SEQ + t)*HID + col] = h2;
            if (t == SEQ-1){
                *(float2*)&hid[b1*HID + col] = make_float2(v0, v1);
                *(float2*)&hid[b2*HID + col] = make_float2(v2, v3);
            }
        }
        __syncthreads();
        if (tid == 0) red_rel(&cnt[t]);
    }
}

extern "C" void kernel_launch(void* const* d_in, const int* in_sizes, int n_in,
                              void* d_out, int out_size)
{
    const int*   ids  = (const int*)  d_in[0];
    const float* emb  = (const float*)d_in[1];
    const float* Wih0 = (const float*)d_in[2];
    const float* Whh0 = (const float*)d_in[3];
    const float* bih0 = (const float*)d_in[4];
    const float* bhh0 = (const float*)d_in[5];
    const float* Wih1 = (const float*)d_in[6];
    const float* Whh1 = (const float*)d_in[7];
    const float* bih1 = (const float*)d_in[8];
    const float* bhh1 = (const float*)d_in[9];
    const float* fcw  = (const float*)d_in[10];
    const float* fcb  = (const float*)d_in[11];
    float* out = (float*)d_out;

    float *logits = out;
    float *hid0   = out + (size_t)NTOK*VOCAB;
    float *hid1   = hid0 + BATCH*HID;

    __half *xp, *y0p, *y1p, *wi0, *wh0, *wi1, *wh1, *fcwh;
    float  *prep, *b0p, *b1p;
    unsigned *c0p, *c1p;
    cudaGetSymbolAddress((void**)&xp,  g_x);
    cudaGetSymbolAddress((void**)&y0p, g_y0);
    cudaGetSymbolAddress((void**)&y1p, g_y1);
    cudaGetSymbolAddress((void**)&prep,g_pre);
    cudaGetSymbolAddress((void**)&wi0, g_Wih0h);
    cudaGetSymbolAddress((void**)&wh0, g_Whh0h);
    cudaGetSymbolAddress((void**)&wi1, g_Wih1h);
    cudaGetSymbolAddress((void**)&wh1, g_Whh1h);
    cudaGetSymbolAddress((void**)&fcwh,g_fcwh);
    cudaGetSymbolAddress((void**)&b0p, g_b0);
    cudaGetSymbolAddress((void**)&b1p, g_b1);
    cudaGetSymbolAddress((void**)&c0p, g_cnt0);
    cudaGetSymbolAddress((void**)&c1p, g_cnt1);

    const int RNN_SMEM = (32+16)*(HID+8)*2;  // ~99 KB
    cudaFuncSetAttribute(rnn_layer, cudaFuncAttributeMaxDynamicSharedMemorySize, RNN_SMEM);

    prep_kernel<<<1024,256>>>(Wih0,Whh0,bih0,bhh0,Wih1,Whh1,bih1,bhh1,fcw);
    embed_kernel<<<NTOK,256>>>(ids, emb);

    dim3 gp(NTOK/128, HID/128);
    gemm_tn<true ><<<gp,256>>>(xp,  wi0, b0p, prep, HID, EMBD);
    rnn_layer<<<32,256,RNN_SMEM>>>(prep, wh0, y0p, hid0, c0p);
    gemm_tn<true ><<<gp,256>>>(y0p, wi1, b1p, prep, HID, HID);
    rnn_layer<<<32,256,RNN_SMEM>>>(prep, wh1, y1p, hid1, c1p);

    dim3 gf(NTOK/128, VOCAB/128);
    gemm_tn<false><<<gf,256>>>(y1p, fcwh, fcb, logits, VOCAB, HID);
}

// round 4
// speedup vs baseline: 1.2995x; 1.2995x over previous
#include <cuda_runtime.h>
#include <cuda_fp16.h>
#include <cstdint>

#define VOCAB 32000
#define EMBD  1024
#define HID   1024
#define BATCH 16
#define SEQ   512
#define NTOK  (BATCH*SEQ)

__device__ __half g_x   [(size_t)NTOK*EMBD];
__device__ __half g_y1  [(size_t)NTOK*HID];
__device__ float  g_pre [(size_t)NTOK*HID];
__device__ __half g_hall0[(size_t)SEQ*BATCH*HID];  // [t][b][h] layer0 outputs
__device__ __half g_hall1[(size_t)SEQ*BATCH*HID];  // [t][b][h] layer1 outputs
__device__ __half g_Wih0h[(size_t)HID*EMBD];
__device__ __half g_Whh0h[(size_t)HID*HID];
__device__ __half g_Wih1h[(size_t)HID*HID];
__device__ __half g_Whh1h[(size_t)HID*HID];
__device__ __half g_fcwh [(size_t)VOCAB*HID];
__device__ float  g_b0[HID];
__device__ float  g_b1[HID];
__device__ unsigned g_cnt0[SEQ];
__device__ unsigned g_cnt1[SEQ];

__device__ __forceinline__ uint32_t smem_u32(const void* p){
    return (uint32_t)__cvta_generic_to_shared(p);
}
__device__ __forceinline__ void ldsm_x4(uint32_t &r0,uint32_t &r1,uint32_t &r2,uint32_t &r3,uint32_t a){
    asm volatile("ldmatrix.sync.aligned.m8n8.x4.shared.b16 {%0,%1,%2,%3}, [%4];"
        : "=r"(r0),"=r"(r1),"=r"(r2),"=r"(r3) : "r"(a));
}
__device__ __forceinline__ void ldsm_x2(uint32_t &r0,uint32_t &r1,uint32_t a){
    asm volatile("ldmatrix.sync.aligned.m8n8.x2.shared.b16 {%0,%1}, [%2];"
        : "=r"(r0),"=r"(r1) : "r"(a));
}
__device__ __forceinline__ void mma16816(float c[4], const uint32_t a[4], const uint32_t b[2]){
    asm volatile(
      "mma.sync.aligned.m16n8k16.row.col.f32.f16.f16.f32 "
      "{%0,%1,%2,%3}, {%4,%5,%6,%7}, {%8,%9}, {%0,%1,%2,%3};"
      : "+f"(c[0]), "+f"(c[1]), "+f"(c[2]), "+f"(c[3])
      : "r"(a[0]), "r"(a[1]), "r"(a[2]), "r"(a[3]), "r"(b[0]), "r"(b[1]));
}
__device__ __forceinline__ void cp_async16(void* s, const void* g){
    asm volatile("cp.async.cg.shared.global [%0], [%1], 16;" :: "r"(smem_u32(s)), "l"(g));
}
#define CP_COMMIT() asm volatile("cp.async.commit_group;")
#define CP_WAIT0()  asm volatile("cp.async.wait_group 0;")

__device__ __forceinline__ unsigned ld_acq(const unsigned* p){
    unsigned v;
    asm volatile("ld.acquire.gpu.global.u32 %0, [%1];" : "=r"(v) : "l"(p) : "memory");
    return v;
}
__device__ __forceinline__ void red_rel(unsigned* p){
    asm volatile("red.release.gpu.global.add.u32 [%0], 1;" :: "l"(p) : "memory");
}

// ---- prep: weights -> fp16, bias sums, counters reset -----------------------
__global__ void prep_kernel(const float* __restrict__ Wih0, const float* __restrict__ Whh0,
                            const float* __restrict__ bih0, const float* __restrict__ bhh0,
                            const float* __restrict__ Wih1, const float* __restrict__ Whh1,
                            const float* __restrict__ bih1, const float* __restrict__ bhh1,
                            const float* __restrict__ fcw)
{
    size_t gtid = (size_t)blockIdx.x*blockDim.x + threadIdx.x;
    size_t gs   = (size_t)gridDim.x*blockDim.x;
    const size_t NW = (size_t)HID*HID;
    for (size_t i = gtid; i < NW; i += gs){
        g_Wih0h[i] = __float2half(Wih0[i]);
        g_Whh0h[i] = __float2half(Whh0[i]);
        g_Wih1h[i] = __float2half(Wih1[i]);
        g_Whh1h[i] = __float2half(Whh1[i]);
    }
    const size_t NF4 = (size_t)VOCAB*HID/4;
    for (size_t i = gtid; i < NF4; i += gs){
        float4 v = ((const float4*)fcw)[i];
        __half2* dst = (__half2*)&g_fcwh[i*4];
        dst[0] = __floats2half2_rn(v.x, v.y);
        dst[1] = __floats2half2_rn(v.z, v.w);
    }
    for (size_t i = gtid; i < HID; i += gs){
        g_b0[i] = bih0[i] + bhh0[i];
        g_b1[i] = bih1[i] + bhh1[i];
    }
    for (size_t i = gtid; i < SEQ; i += gs){ g_cnt0[i] = 0; g_cnt1[i] = 0; }
}

// ---- embedding gather -------------------------------------------------------
__global__ void embed_kernel(const int* __restrict__ ids, const float* __restrict__ emb)
{
    int m = blockIdx.x;
    int row = ids[m];
    const float4* src = (const float4*)(emb + (size_t)row*EMBD);
    __half2* dst = (__half2*)(g_x + (size_t)m*EMBD);
    int t = threadIdx.x;
    float4 v = src[t];
    dst[t*2 + 0] = __floats2half2_rn(v.x, v.y);
    dst[t*2 + 1] = __floats2half2_rn(v.z, v.w);
}

// ---- C[M,N] = A[M,K]*B[N,K]^T + bias; 128x128x32 tile, 8 warps --------------
template<bool TIME_MAJOR>
__global__ void __launch_bounds__(256) gemm_tn(
    const __half* __restrict__ A, const __half* __restrict__ B,
    const float* __restrict__ bias, float* __restrict__ C, int N, int K)
{
    constexpr int BM=128, BN=128, BK=32, STR=BK+8;
    __shared__ __align__(16) __half As[2][BM*STR];
    __shared__ __align__(16) __half Bs[2][BN*STR];

    const int tid  = threadIdx.x;
    const int lane = tid & 31, wid = tid >> 5;
    const int m0 = blockIdx.x*BM, n0 = blockIdx.y*BN;
    const int wm = (wid & 3)*32, wn = (wid >> 2)*64;

    float acc[2][8][4];
    #pragma unroll
    for (int a=0;a<2;a++) for (int b=0;b<8;b++) for (int c=0;c<4;c++) acc[a][b][c]=0.f;

    auto load_tiles = [&](int buf, int k0){
        #pragma unroll
        for (int i=0;i<2;i++){
            int c = tid*2 + i;
            int r = c >> 2, kc = (c & 3)*8;
            cp_async16(&As[buf][r*STR + kc], &A[(size_t)(m0+r)*K + k0 + kc]);
            cp_async16(&Bs[buf][r*STR + kc], &B[(size_t)(n0+r)*K + k0 + kc]);
        }
    };

    const int KT = K/BK;
    load_tiles(0, 0); CP_COMMIT();
    int buf = 0;
    for (int kt = 0; kt < KT; kt++){
        CP_WAIT0(); __syncthreads();
        if (kt + 1 < KT){ load_tiles(buf^1, (kt+1)*BK); CP_COMMIT(); }
        #pragma unroll
        for (int kk = 0; kk < 2; kk++){
            uint32_t a[2][4];
            #pragma unroll
            for (int mi=0; mi<2; mi++){
                int r  = wm + mi*16 + (lane & 15);
                int kc = kk*16 + (lane >> 4)*8;
                ldsm_x4(a[mi][0],a[mi][1],a[mi][2],a[mi][3], smem_u32(&As[buf][r*STR + kc]));
            }
            uint32_t bb[8][2];
            #pragma unroll
            for (int np=0; np<4; np++){
                int gq = lane >> 3;
                int nr = wn + np*16 + (lane & 7) + ((gq >> 1) << 3);
                int kc = kk*16 + ((gq & 1) << 3);
                uint32_t r0,r1,r2,r3;
                ldsm_x4(r0,r1,r2,r3, smem_u32(&Bs[buf][nr*STR + kc]));
                bb[np*2][0]=r0; bb[np*2][1]=r1; bb[np*2+1][0]=r2; bb[np*2+1][1]=r3;
            }
            #pragma unroll
            for (int mi=0; mi<2; mi++)
                #pragma unroll
                for (int ni=0; ni<8; ni++)
                    mma16816(acc[mi][ni], a[mi], bb[ni]);
        }
        buf ^= 1;
    }

    #pragma unroll
    for (int mi=0; mi<2; mi++){
        #pragma unroll
        for (int ni=0; ni<8; ni++){
            int col = n0 + wn + ni*8 + (lane & 3)*2;
            float bv0 = bias[col], bv1 = bias[col+1];
            #pragma unroll
            for (int h=0; h<2; h++){
                int row = m0 + wm + mi*16 + (lane >> 2) + h*8;
                size_t orow = TIME_MAJOR ? (size_t)((row & (SEQ-1))*BATCH + (row >> 9))
                                         : (size_t)row;
                float2 v = make_float2(acc[mi][ni][h*2+0] + bv0,
                                       acc[mi][ni][h*2+1] + bv1);
                *(float2*)&C[orow*(size_t)N + col] = v;
            }
        }
    }
}

// ---- fused 2-layer persistent RNN: 64 CTAs ---------------------------------
// blocks 0..31  = layer 0 (K=1024: Whh0),  pre from g_pre (time-major)
// blocks 32..63 = layer 1 (K=2048: [Wih1|Whh1]), A = [y0(t), h1(t-1)], lags 1 step
__global__ void __launch_bounds__(256,1) rnn_fused(
    const float* __restrict__ pre0, float* __restrict__ hid0, float* __restrict__ hid1)
{
    extern __shared__ __align__(16) __half sm[];
    __shared__ float red[4][32][4];

    const int tid  = threadIdx.x;
    const int lane = tid & 31, wid = tid >> 5;
    const int layer = blockIdx.x >> 5;
    const int cb   = (blockIdx.x & 31) * 32;
    const int nw   = (wid & 3) * 8;
    const int kh   = wid >> 2;

    const int K  = layer ? 2048 : 1024;
    const int SK = K + 8;
    __half* Ws = sm;             // [32][SK]
    __half* Hs = sm + 32*SK;     // [16][SK]

    // stage weight slice once
    if (layer == 0){
        for (int c = tid; c < 32*128; c += 256){
            int n = c >> 7, q = c & 127;
            *(uint4*)&Ws[n*SK + q*8] = *(const uint4*)&g_Whh0h[(size_t)(cb+n)*HID + q*8];
        }
    } else {
        for (int c = tid; c < 32*128; c += 256){
            int n = c >> 7, q = c & 127;
            *(uint4*)&Ws[n*SK + q*8]        = *(const uint4*)&g_Wih1h[(size_t)(cb+n)*HID + q*8];
            *(uint4*)&Ws[n*SK + 1024 + q*8] = *(const uint4*)&g_Whh1h[(size_t)(cb+n)*HID + q*8];
        }
    }
    __syncthreads();

    // epilogue lane geometry
    const int b1 = lane >> 2, b2 = b1 + 8;
    const int col = cb + nw + (lane & 3)*2;
    float2 bias1 = make_float2(0.f, 0.f);
    if (layer == 1 && kh == 0) bias1 = *(const float2*)&g_b1[col];

    const int KTH = K / 32;     // k-tiles of 16 per k-half warp group

    for (int t = 0; t < SEQ; t++){
        // layer0: prefetch pre(t) before any waiting
        float2 p1, p2;
        if (layer == 0 && kh == 0){
            p1 = __ldg((const float2*)&pre0[((size_t)t*BATCH + b1)*HID + col]);
            p2 = __ldg((const float2*)&pre0[((size_t)t*BATCH + b2)*HID + col]);
        } else { p1 = bias1; p2 = bias1; }

        float acc[4] = {0.f,0.f,0.f,0.f};
        bool do_mma = (layer == 1) || (t > 0);

        if (do_mma){
            if (layer == 0){
                while (ld_acq(&g_cnt0[t-1]) < 32) {}
                const __half* hsrc = &g_hall0[(size_t)(t-1)*BATCH*HID];
                for (int c = tid; c < 16*128; c += 256){
                    int b = c >> 7, q = c & 127;
                    float4 v = __ldcg((const float4*)&hsrc[(size_t)b*HID + q*8]);
                    *(float4*)&Hs[b*SK + q*8] = v;
                }
            } else {
                while (ld_acq(&g_cnt0[t]) < 32) {}
                if (t > 0){ while (ld_acq(&g_cnt1[t-1]) < 32) {} }
                const __half* ysrc = &g_hall0[(size_t)t*BATCH*HID];
                for (int c = tid; c < 16*128; c += 256){
                    int b = c >> 7, q = c & 127;
                    float4 v = __ldcg((const float4*)&ysrc[(size_t)b*HID + q*8]);
                    *(float4*)&Hs[b*SK + q*8] = v;
                }
                if (t > 0){
                    const __half* hsrc = &g_hall1[(size_t)(t-1)*BATCH*HID];
                    for (int c = tid; c < 16*128; c += 256){
                        int b = c >> 7, q = c & 127;
                        float4 v = __ldcg((const float4*)&hsrc[(size_t)b*HID + q*8]);
                        *(float4*)&Hs[b*SK + 1024 + q*8] = v;
                    }
                } else {
                    float4 z = make_float4(0.f,0.f,0.f,0.f);
                    for (int c = tid; c < 16*128; c += 256){
                        int b = c >> 7, q = c & 127;
                        *(float4*)&Hs[b*SK + 1024 + q*8] = z;
                    }
                }
            }
            __syncthreads();

            #pragma unroll 4
            for (int kt = 0; kt < KTH; kt++){
                int kg = kh*KTH + kt;
                uint32_t a[4];
                ldsm_x4(a[0],a[1],a[2],a[3],
                        smem_u32(&Hs[(lane&15)*SK + kg*16 + (lane>>4)*8]));
                uint32_t c0,c1;
                ldsm_x2(c0,c1,
                        smem_u32(&Ws[(nw + (lane&7))*SK + kg*16 + (((lane>>3)&1)<<3)]));
                uint32_t bb[2] = {c0,c1};
                mma16816(acc, a, bb);
            }
            if (kh == 1){
                #pragma unroll
                for (int i=0;i<4;i++) red[wid-4][lane][i] = acc[i];
            }
            __syncthreads();
            if (kh == 0){
                #pragma unroll
                for (int i=0;i<4;i++) acc[i] += red[wid][lane][i];
            }
        }

        if (kh == 0){
            float v0 = tanhf(acc[0] + p1.x), v1 = tanhf(acc[1] + p1.y);
            float v2 = tanhf(acc[2] + p2.x), v3 = tanhf(acc[3] + p2.y);
            __half2 h1 = __floats2half2_rn(v0, v1);
            __half2 h2 = __floats2half2_rn(v2, v3);
            __half* hall = layer ? g_hall1 : g_hall0;
            *(__half2*)&hall[((size_t)t*BATCH + b1)*HID + col] = h1;
            *(__half2*)&hall[((size_t)t*BATCH + b2)*HID + col] = h2;
            if (layer == 1){
                *(__half2*)&g_y1[((size_t)b1*SEQ + t)*HID + col] = h1;
                *(__half2*)&g_y1[((size_t)b2*SEQ + t)*HID + col] = h2;
            }
            if (t == SEQ-1){
                float* hd = layer ? hid1 : hid0;
                *(float2*)&hd[b1*HID + col] = make_float2(v0, v1);
                *(float2*)&hd[b2*HID + col] = make_float2(v2, v3);
            }
        }
        __syncthreads();
        if (tid == 0) red_rel(layer ? &g_cnt1[t] : &g_cnt0[t]);
    }
}

extern "C" void kernel_launch(void* const* d_in, const int* in_sizes, int n_in,
                              void* d_out, int out_size)
{
    const int*   ids  = (const int*)  d_in[0];
    const float* emb  = (const float*)d_in[1];
    const float* Wih0 = (const float*)d_in[2];
    const float* Whh0 = (const float*)d_in[3];
    const float* bih0 = (const float*)d_in[4];
    const float* bhh0 = (const float*)d_in[5];
    const float* Wih1 = (const float*)d_in[6];
    const float* Whh1 = (const float*)d_in[7];
    const float* bih1 = (const float*)d_in[8];
    const float* bhh1 = (const float*)d_in[9];
    const float* fcw  = (const float*)d_in[10];
    const float* fcb  = (const float*)d_in[11];
    float* out = (float*)d_out;

    float *logits = out;
    float *hid0   = out + (size_t)NTOK*VOCAB;
    float *hid1   = hid0 + BATCH*HID;

    __half *xp, *y1p, *wi0, *fcwh;
    float  *prep, *b0p;
    cudaGetSymbolAddress((void**)&xp,  g_x);
    cudaGetSymbolAddress((void**)&y1p, g_y1);
    cudaGetSymbolAddress((void**)&prep,g_pre);
    cudaGetSymbolAddress((void**)&wi0, g_Wih0h);
    cudaGetSymbolAddress((void**)&fcwh,g_fcwh);
    cudaGetSymbolAddress((void**)&b0p, g_b0);

    const int RNN_SMEM = (32+16)*(2048+8)*2;  // 197376 B
    static int attr_done = 0;
    cudaFuncSetAttribute(rnn_fused, cudaFuncAttributeMaxDynamicSharedMemorySize, RNN_SMEM);
    (void)attr_done;

    prep_kernel<<<1024,256>>>(Wih0,Whh0,bih0,bhh0,Wih1,Whh1,bih1,bhh1,fcw);
    embed_kernel<<<NTOK,256>>>(ids, emb);

    dim3 gp(NTOK/128, HID/128);
    gemm_tn<true ><<<gp,256>>>(xp, wi0, b0p, prep, HID, EMBD);

    rnn_fused<<<64,256,RNN_SMEM>>>(prep, hid0, hid1);

    dim3 gf(NTOK/128, VOCAB/128);
    gemm_tn<false><<<gf,256>>>(y1p, fcwh, fcb, logits, VOCAB, HID);
}

// round 5
// speedup vs baseline: 1.3763x; 1.0591x over previous
#include <cuda_runtime.h>
#include <cuda_fp16.h>
#include <cstdint>

#define VOCAB 32000
#define EMBD  1024
#define HID   1024
#define BATCH 16
#define SEQ   512
#define NTOK  (BATCH*SEQ)
#define NTILE_N (VOCAB/128)      // 250
#define NTILES  (NTILE_N*64)     // 16000

__device__ __half g_x   [(size_t)NTOK*EMBD];
__device__ __half g_y1  [(size_t)NTOK*HID];
__device__ float  g_pre [(size_t)NTOK*HID];
__device__ __half g_hall0[(size_t)SEQ*BATCH*HID];
__device__ __half g_hall1[(size_t)SEQ*BATCH*HID];
__device__ __half g_Wih0h[(size_t)HID*EMBD];
__device__ __half g_Whh0h[(size_t)HID*HID];
__device__ __half g_Wih1h[(size_t)HID*HID];
__device__ __half g_Whh1h[(size_t)HID*HID];
__device__ __half g_fcwh [(size_t)VOCAB*HID];
__device__ float  g_b0[HID];
__device__ float  g_b1[HID];
__device__ unsigned g_cnt0[SEQ];
__device__ unsigned g_cnt1[SEQ];
__device__ unsigned g_ticket;

__device__ __forceinline__ uint32_t smem_u32(const void* p){
    return (uint32_t)__cvta_generic_to_shared(p);
}
__device__ __forceinline__ void ldsm_x4(uint32_t &r0,uint32_t &r1,uint32_t &r2,uint32_t &r3,uint32_t a){
    asm volatile("ldmatrix.sync.aligned.m8n8.x4.shared.b16 {%0,%1,%2,%3}, [%4];"
        : "=r"(r0),"=r"(r1),"=r"(r2),"=r"(r3) : "r"(a));
}
__device__ __forceinline__ void ldsm_x2(uint32_t &r0,uint32_t &r1,uint32_t a){
    asm volatile("ldmatrix.sync.aligned.m8n8.x2.shared.b16 {%0,%1}, [%2];"
        : "=r"(r0),"=r"(r1) : "r"(a));
}
__device__ __forceinline__ void mma16816(float c[4], const uint32_t a[4], const uint32_t b[2]){
    asm volatile(
      "mma.sync.aligned.m16n8k16.row.col.f32.f16.f16.f32 "
      "{%0,%1,%2,%3}, {%4,%5,%6,%7}, {%8,%9}, {%0,%1,%2,%3};"
      : "+f"(c[0]), "+f"(c[1]), "+f"(c[2]), "+f"(c[3])
      : "r"(a[0]), "r"(a[1]), "r"(a[2]), "r"(a[3]), "r"(b[0]), "r"(b[1]));
}
__device__ __forceinline__ void cp_async16(void* s, const void* g){
    asm volatile("cp.async.cg.shared.global [%0], [%1], 16;" :: "r"(smem_u32(s)), "l"(g));
}
#define CP_COMMIT() asm volatile("cp.async.commit_group;")
#define CP_WAIT0()  asm volatile("cp.async.wait_group 0;")

__device__ __forceinline__ unsigned ld_acq(const unsigned* p){
    unsigned v;
    asm volatile("ld.acquire.gpu.global.u32 %0, [%1];" : "=r"(v) : "l"(p) : "memory");
    return v;
}
__device__ __forceinline__ void red_rel(unsigned* p){
    asm volatile("red.release.gpu.global.add.u32 [%0], 1;" :: "l"(p) : "memory");
}

// ---- prep --------------------------------------------------------------------
__global__ void prep_kernel(const float* __restrict__ Wih0, const float* __restrict__ Whh0,
                            const float* __restrict__ bih0, const float* __restrict__ bhh0,
                            const float* __restrict__ Wih1, const float* __restrict__ Whh1,
                            const float* __restrict__ bih1, const float* __restrict__ bhh1,
                            const float* __restrict__ fcw)
{
    size_t gtid = (size_t)blockIdx.x*blockDim.x + threadIdx.x;
    size_t gs   = (size_t)gridDim.x*blockDim.x;
    const size_t NW = (size_t)HID*HID;
    for (size_t i = gtid; i < NW; i += gs){
        g_Wih0h[i] = __float2half(Wih0[i]);
        g_Whh0h[i] = __float2half(Whh0[i]);
        g_Wih1h[i] = __float2half(Wih1[i]);
        g_Whh1h[i] = __float2half(Whh1[i]);
    }
    const size_t NF4 = (size_t)VOCAB*HID/4;
    for (size_t i = gtid; i < NF4; i += gs){
        float4 v = ((const float4*)fcw)[i];
        __half2* dst = (__half2*)&g_fcwh[i*4];
        dst[0] = __floats2half2_rn(v.x, v.y);
        dst[1] = __floats2half2_rn(v.z, v.w);
    }
    for (size_t i = gtid; i < HID; i += gs){
        g_b0[i] = bih0[i] + bhh0[i];
        g_b1[i] = bih1[i] + bhh1[i];
    }
    for (size_t i = gtid; i < SEQ; i += gs){ g_cnt0[i] = 0; g_cnt1[i] = 0; }
    if (gtid == 0) g_ticket = 0;
}

// ---- embedding ----------------------------------------------------------------
__global__ void embed_kernel(const int* __restrict__ ids, const float* __restrict__ emb)
{
    int m = blockIdx.x;
    int row = ids[m];
    const float4* src = (const float4*)(emb + (size_t)row*EMBD);
    __half2* dst = (__half2*)(g_x + (size_t)m*EMBD);
    int t = threadIdx.x;
    float4 v = src[t];
    dst[t*2 + 0] = __floats2half2_rn(v.x, v.y);
    dst[t*2 + 1] = __floats2half2_rn(v.z, v.w);
}

// ---- shared 128x128 GEMM tile: C = A[M,K]*B[N,K]^T + bias ----------------------
__device__ __forceinline__ void gemm_tile(
    const __half* __restrict__ A, const __half* __restrict__ B,
    const float* __restrict__ bias, float* __restrict__ C,
    int N, int K, int m0, int n0, bool time_major, __half* sm)
{
    constexpr int BM=128, BN=128, BK=32, STR=BK+8;
    __half* As = sm;                   // [2][BM*STR]
    __half* Bs = sm + 2*BM*STR;        // [2][BN*STR]

    const int tid  = threadIdx.x;
    const int lane = tid & 31, wid = tid >> 5;
    const int wm = (wid & 3)*32, wn = (wid >> 2)*64;

    float acc[2][8][4];
    #pragma unroll
    for (int a=0;a<2;a++) for (int b=0;b<8;b++) for (int c=0;c<4;c++) acc[a][b][c]=0.f;

    auto load_tiles = [&](int buf, int k0){
        __half* Ab = As + buf*BM*STR;
        __half* Bb = Bs + buf*BN*STR;
        #pragma unroll
        for (int i=0;i<2;i++){
            int c = tid*2 + i;
            int r = c >> 2, kc = (c & 3)*8;
            cp_async16(&Ab[r*STR + kc], &A[(size_t)(m0+r)*K + k0 + kc]);
            cp_async16(&Bb[r*STR + kc], &B[(size_t)(n0+r)*K + k0 + kc]);
        }
    };

    const int KT = K/BK;
    load_tiles(0, 0); CP_COMMIT();
    int buf = 0;
    for (int kt = 0; kt < KT; kt++){
        CP_WAIT0(); __syncthreads();
        if (kt + 1 < KT){ load_tiles(buf^1, (kt+1)*BK); CP_COMMIT(); }
        __half* Ab = As + buf*BM*STR;
        __half* Bb = Bs + buf*BN*STR;
        #pragma unroll
        for (int kk = 0; kk < 2; kk++){
            uint32_t a[2][4];
            #pragma unroll
            for (int mi=0; mi<2; mi++){
                int r  = wm + mi*16 + (lane & 15);
                int kc = kk*16 + (lane >> 4)*8;
                ldsm_x4(a[mi][0],a[mi][1],a[mi][2],a[mi][3], smem_u32(&Ab[r*STR + kc]));
            }
            uint32_t bb[8][2];
            #pragma unroll
            for (int np=0; np<4; np++){
                int gq = lane >> 3;
                int nr = wn + np*16 + (lane & 7) + ((gq >> 1) << 3);
                int kc = kk*16 + ((gq & 1) << 3);
                uint32_t r0,r1,r2,r3;
                ldsm_x4(r0,r1,r2,r3, smem_u32(&Bb[nr*STR + kc]));
                bb[np*2][0]=r0; bb[np*2][1]=r1; bb[np*2+1][0]=r2; bb[np*2+1][1]=r3;
            }
            #pragma unroll
            for (int mi=0; mi<2; mi++)
                #pragma unroll
                for (int ni=0; ni<8; ni++)
                    mma16816(acc[mi][ni], a[mi], bb[ni]);
        }
        buf ^= 1;
        __syncthreads();
    }

    #pragma unroll
    for (int mi=0; mi<2; mi++){
        #pragma unroll
        for (int ni=0; ni<8; ni++){
            int col = n0 + wn + ni*8 + (lane & 3)*2;
            float bv0 = bias[col], bv1 = bias[col+1];
            #pragma unroll
            for (int h=0; h<2; h++){
                int row = m0 + wm + mi*16 + (lane >> 2) + h*8;
                size_t orow = time_major ? (size_t)((row & (SEQ-1))*BATCH + (row >> 9))
                                         : (size_t)row;
                float2 v = make_float2(acc[mi][ni][h*2+0] + bv0,
                                       acc[mi][ni][h*2+1] + bv1);
                *(float2*)&C[orow*(size_t)N + col] = v;
            }
        }
    }
}

// ---- pre-projection GEMM kernel (time-major out) -------------------------------
__global__ void __launch_bounds__(256) gemm_pre(
    const __half* __restrict__ A, const __half* __restrict__ B,
    const float* __restrict__ bias, float* __restrict__ C, int N, int K)
{
    extern __shared__ __align__(16) __half sm[];
    gemm_tile(A, B, bias, C, N, K, blockIdx.x*128, blockIdx.y*128, true, sm);
}

// ---- fc worker: ticket-driven vocab GEMM gated on y1 flags ---------------------
__device__ void fc_worker(const float* __restrict__ fcb, float* __restrict__ logits, __half* sm)
{
    __shared__ unsigned s_tk;
    while (true){
        __syncthreads();
        if (threadIdx.x == 0) s_tk = atomicAdd(&g_ticket, 1u);
        __syncthreads();
        unsigned idx = s_tk;
        if (idx >= NTILES) return;
        int ny = idx % NTILE_N;
        int rem = idx / NTILE_N;
        int b = rem & 15, q = rem >> 4;         // q = time quarter, slowest
        if (threadIdx.x == 0){ while (ld_acq(&g_cnt1[q*128 + 127]) < 32) {} }
        __syncthreads();
        gemm_tile(g_y1, g_fcwh, fcb, logits, VOCAB, HID,
                  b*SEQ + q*128, ny*128, false, sm);
    }
}

// ---- fused persistent kernel: 148 CTAs -----------------------------------------
// blocks 0..31: RNN layer0; 32..63: RNN layer1; all blocks end as fc workers
__global__ void __launch_bounds__(256,1) rnn_fc_fused(
    const float* __restrict__ pre0, const float* __restrict__ fcb,
    float* __restrict__ logits, float* __restrict__ hid0, float* __restrict__ hid1)
{
    extern __shared__ __align__(16) __half sm[];
    __shared__ float red[4][32][4];

    if (blockIdx.x < 64){
        const int tid  = threadIdx.x;
        const int lane = tid & 31, wid = tid >> 5;
        const int layer = blockIdx.x >> 5;
        const int cb   = (blockIdx.x & 31) * 32;
        const int nw   = (wid & 3) * 8;
        const int kh   = wid >> 2;

        const int K  = layer ? 2048 : 1024;
        const int SK = K + 8;
        __half* Ws = sm;             // [32][SK]
        __half* Hs = sm + 32*SK;     // [16][SK]

        if (layer == 0){
            for (int c = tid; c < 32*128; c += 256){
                int n = c >> 7, q = c & 127;
                *(uint4*)&Ws[n*SK + q*8] = *(const uint4*)&g_Whh0h[(size_t)(cb+n)*HID + q*8];
            }
        } else {
            for (int c = tid; c < 32*128; c += 256){
                int n = c >> 7, q = c & 127;
                *(uint4*)&Ws[n*SK + q*8]        = *(const uint4*)&g_Wih1h[(size_t)(cb+n)*HID + q*8];
                *(uint4*)&Ws[n*SK + 1024 + q*8] = *(const uint4*)&g_Whh1h[(size_t)(cb+n)*HID + q*8];
            }
        }
        __syncthreads();

        const int b1 = lane >> 2, b2 = b1 + 8;
        const int col = cb + nw + (lane & 3)*2;
        float2 bias1 = make_float2(0.f, 0.f);
        if (layer == 1 && kh == 0) bias1 = *(const float2*)&g_b1[col];
        const int KTH = K / 32;

        for (int t = 0; t < SEQ; t++){
            float2 p1, p2;
            if (layer == 0 && kh == 0){
                p1 = __ldg((const float2*)&pre0[((size_t)t*BATCH + b1)*HID + col]);
                p2 = __ldg((const float2*)&pre0[((size_t)t*BATCH + b2)*HID + col]);
            } else { p1 = bias1; p2 = bias1; }

            float acc[4] = {0.f,0.f,0.f,0.f};
            bool do_mma = (layer == 1) || (t > 0);

            if (do_mma){
                if (layer == 0){
                    while (ld_acq(&g_cnt0[t-1]) < 32) {}
                    const __half* hsrc = &g_hall0[(size_t)(t-1)*BATCH*HID];
                    for (int c = tid; c < 16*128; c += 256){
                        int b = c >> 7, q = c & 127;
                        float4 v = __ldcg((const float4*)&hsrc[(size_t)b*HID + q*8]);
                        *(float4*)&Hs[b*SK + q*8] = v;
                    }
                } else {
                    while (ld_acq(&g_cnt0[t]) < 32) {}
                    if (t > 0){ while (ld_acq(&g_cnt1[t-1]) < 32) {} }
                    const __half* ysrc = &g_hall0[(size_t)t*BATCH*HID];
                    for (int c = tid; c < 16*128; c += 256){
                        int b = c >> 7, q = c & 127;
                        float4 v = __ldcg((const float4*)&ysrc[(size_t)b*HID + q*8]);
                        *(float4*)&Hs[b*SK + q*8] = v;
                    }
                    if (t > 0){
                        const __half* hsrc = &g_hall1[(size_t)(t-1)*BATCH*HID];
                        for (int c = tid; c < 16*128; c += 256){
                            int b = c >> 7, q = c & 127;
                            float4 v = __ldcg((const float4*)&hsrc[(size_t)b*HID + q*8]);
                            *(float4*)&Hs[b*SK + 1024 + q*8] = v;
                        }
                    } else {
                        float4 z = make_float4(0.f,0.f,0.f,0.f);
                        for (int c = tid; c < 16*128; c += 256){
                            int b = c >> 7, q = c & 127;
                            *(float4*)&Hs[b*SK + 1024 + q*8] = z;
                        }
                    }
                }
                __syncthreads();

                #pragma unroll 4
                for (int kt = 0; kt < KTH; kt++){
                    int kg = kh*KTH + kt;
                    uint32_t a[4];
                    ldsm_x4(a[0],a[1],a[2],a[3],
                            smem_u32(&Hs[(lane&15)*SK + kg*16 + (lane>>4)*8]));
                    uint32_t c0,c1;
                    ldsm_x2(c0,c1,
                            smem_u32(&Ws[(nw + (lane&7))*SK + kg*16 + (((lane>>3)&1)<<3)]));
                    uint32_t bb[2] = {c0,c1};
                    mma16816(acc, a, bb);
                }
                if (kh == 1){
                    #pragma unroll
                    for (int i=0;i<4;i++) red[wid-4][lane][i] = acc[i];
                }
                __syncthreads();
                if (kh == 0){
                    #pragma unroll
                    for (int i=0;i<4;i++) acc[i] += red[wid][lane][i];
                }
            }

            if (kh == 0){
                float v0 = tanhf(acc[0] + p1.x), v1 = tanhf(acc[1] + p1.y);
                float v2 = tanhf(acc[2] + p2.x), v3 = tanhf(acc[3] + p2.y);
                __half2 h1 = __floats2half2_rn(v0, v1);
                __half2 h2 = __floats2half2_rn(v2, v3);
                __half* hall = layer ? g_hall1 : g_hall0;
                *(__half2*)&hall[((size_t)t*BATCH + b1)*HID + col] = h1;
                *(__half2*)&hall[((size_t)t*BATCH + b2)*HID + col] = h2;
                if (layer == 1){
                    *(__half2*)&g_y1[((size_t)b1*SEQ + t)*HID + col] = h1;
                    *(__half2*)&g_y1[((size_t)b2*SEQ + t)*HID + col] = h2;
                }
                if (t == SEQ-1){
                    float* hd = layer ? hid1 : hid0;
                    *(float2*)&hd[b1*HID + col] = make_float2(v0, v1);
                    *(float2*)&hd[b2*HID + col] = make_float2(v2, v3);
                }
            }
            __syncthreads();
            if (tid == 0) red_rel(layer ? &g_cnt1[t] : &g_cnt0[t]);
        }
    }

    // everyone becomes an fc worker
    fc_worker(fcb, logits, sm);
}

extern "C" void kernel_launch(void* const* d_in, const int* in_sizes, int n_in,
                              void* d_out, int out_size)
{
    const int*   ids  = (const int*)  d_in[0];
    const float* emb  = (const float*)d_in[1];
    const float* Wih0 = (const float*)d_in[2];
    const float* Whh0 = (const float*)d_in[3];
    const float* bih0 = (const float*)d_in[4];
    const float* bhh0 = (const float*)d_in[5];
    const float* Wih1 = (const float*)d_in[6];
    const float* Whh1 = (const float*)d_in[7];
    const float* bih1 = (const float*)d_in[8];
    const float* bhh1 = (const float*)d_in[9];
    const float* fcw  = (const float*)d_in[10];
    const float* fcb  = (const float*)d_in[11];
    float* out = (float*)d_out;

    float *logits = out;
    float *hid0   = out + (size_t)NTOK*VOCAB;
    float *hid1   = hid0 + BATCH*HID;

    __half *xp, *wi0;
    float  *prep, *b0p;
    cudaGetSymbolAddress((void**)&xp,  g_x);
    cudaGetSymbolAddress((void**)&prep,g_pre);
    cudaGetSymbolAddress((void**)&wi0, g_Wih0h);
    cudaGetSymbolAddress((void**)&b0p, g_b0);

    const int RNN_SMEM  = (32+16)*(2048+8)*2;   // 197376 B
    const int GEMM_SMEM = 4*128*40*2;           // 40960 B
    cudaFuncSetAttribute(rnn_fc_fused, cudaFuncAttributeMaxDynamicSharedMemorySize, RNN_SMEM);

    prep_kernel<<<1024,256>>>(Wih0,Whh0,bih0,bhh0,Wih1,Whh1,bih1,bhh1,fcw);
    embed_kernel<<<NTOK,256>>>(ids, emb);

    dim3 gp(NTOK/128, HID/128);
    gemm_pre<<<gp,256,GEMM_SMEM>>>(xp, wi0, b0p, prep, HID, EMBD);

    rnn_fc_fused<<<148,256,RNN_SMEM>>>(prep, fcb, logits, hid0, hid1);
}